// round 12
// baseline (speedup 1.0000x reference)
#include <cuda_runtime.h>
#include <cuda_bf16.h>
#include <math_constants.h>
#include <cstdint>

#define BB 8
#define EE 100
#define FPAD 4096
#define NTILE 64          // n rows per CTA tile
#define FCH 128           // f cols per chunk
#define FSPLIT 2
#define KROW 128          // bf16 per logical row (2 halves of 64)
#define NKS 7             // 7 x k16 = 112 (zeros past 99 contribute 0)

// smem layout
#define ENT_HALF 8192                   // 64 rows x 128B
#define FACT_HALF 16384                 // 128 rows x 128B
#define ENT_BYTES (2*ENT_HALF)          // 16KB, contiguous per n-tile
#define FACT_BUF (2*FACT_HALF)          // 32KB, contiguous per f-chunk
#define SM_ENT 0
#define SM_FACT ENT_BYTES               // 2 buffers
#define SM_A (SM_FACT + 2*FACT_BUF)     // 2 buffers of [128 f][8 b] bf16
#define A_BUF 2048
#define SM_MBAR (SM_A + 2*A_BUF)        // full0, full1, empty0, empty1 (8B each)
#define SM_TOTAL (SM_MBAR + 32)         // 86048 B (x2 CTAs/SM)

// ---- device scratch ----
__device__ __nv_bfloat16 g_Ab[2][FPAD][BB];    // A transposed (bf16), +INF for f>=F
__device__ float g_e2[FPAD];
__device__ float g_min[2][BB][FPAD];
// PRE-SWIZZLED tiled layouts (written by k_prep, bulk-copied by k_main):
// g_eb: [tile(64 rows)][half][8KB swizzled]   (-2*ent)
// g_fb: [z][chunk(128 rows)][half][16KB swizzled]
__device__ __nv_bfloat16 g_eb[FPAD * KROW];
__device__ __nv_bfloat16 g_fb[2][FPAD * KROW];
__device__ int g_cnt[2][FPAD / NTILE];         // arrival counters per (z, n-tile)

// ---- helpers ----
__device__ __forceinline__ unsigned swz(unsigned b) { return b ^ ((b >> 3) & 0x70); }
__device__ __forceinline__ unsigned smem_u32(const void* p) {
  return (unsigned)__cvta_generic_to_shared(p);
}
__device__ __forceinline__ void mbar_init(unsigned a, unsigned cnt) {
  asm volatile("mbarrier.init.shared.b64 [%0], %1;" :: "r"(a), "r"(cnt) : "memory");
}
__device__ __forceinline__ void mbar_expect(unsigned a, unsigned tx) {
  asm volatile("mbarrier.arrive.expect_tx.shared.b64 _, [%0], %1;"
               :: "r"(a), "r"(tx) : "memory");
}
__device__ __forceinline__ void mbar_arrive(unsigned a) {
  asm volatile("mbarrier.arrive.release.cta.shared::cta.b64 _, [%0];"
               :: "r"(a) : "memory");
}
__device__ __forceinline__ void bulk_g2s(unsigned dst, const void* src,
                                         unsigned bytes, unsigned mbar) {
  asm volatile(
    "cp.async.bulk.shared::cluster.global.mbarrier::complete_tx::bytes "
    "[%0], [%1], %2, [%3];"
    :: "r"(dst), "l"(src), "r"(bytes), "r"(mbar) : "memory");
}
__device__ __forceinline__ void mwait(unsigned a, unsigned par) {
  asm volatile("{\n\t.reg .pred P;\n\t"
               "W%=:\n\tmbarrier.try_wait.parity.acquire.cta.shared::cta.b64 P, [%0], %1, 0x989680;\n\t"
               "@P bra.uni D%=;\n\tbra.uni W%=;\n\tD%=:\n\t}"
               :: "r"(a), "r"(par) : "memory");
}
__device__ __forceinline__ void ldmx4(uint32_t* r, unsigned addr) {
  asm volatile("ldmatrix.sync.aligned.m8n8.x4.shared.b16 {%0,%1,%2,%3}, [%4];"
               : "=r"(r[0]), "=r"(r[1]), "=r"(r[2]), "=r"(r[3]) : "r"(addr));
}
__device__ __forceinline__ void mma16816(float* c, const uint32_t* a,
                                         uint32_t b0, uint32_t b1) {
  asm volatile("mma.sync.aligned.m16n8k16.row.col.f32.bf16.bf16.f32 "
               "{%0,%1,%2,%3}, {%4,%5,%6,%7}, {%8,%9}, {%0,%1,%2,%3};"
               : "+f"(c[0]), "+f"(c[1]), "+f"(c[2]), "+f"(c[3])
               : "r"(a[0]), "r"(a[1]), "r"(a[2]), "r"(a[3]), "r"(b0), "r"(b1));
}
__device__ __forceinline__ uint32_t bcvt2(float x) {
  uint32_t r; asm("cvt.rn.bf16x2.f32 %0, %1, %1;" : "=r"(r) : "f"(x)); return r;
}
__device__ __forceinline__ uint32_t addbf2(uint32_t a, uint32_t b) {
  uint32_t r; asm("add.rn.bf16x2 %0, %1, %2;" : "=r"(r) : "r"(a), "r"(b)); return r;
}
__device__ __forceinline__ uint32_t minbf2(uint32_t a, uint32_t b) {
  uint32_t r; asm("min.bf16x2 %0, %1, %2;" : "=r"(r) : "r"(a), "r"(b)); return r;
}
__device__ __forceinline__ void atomicMinF(float* addr, float v) {
  if (v >= 0.0f) atomicMin((int*)addr, __float_as_int(v));
  else           atomicMax((unsigned int*)addr, __float_as_uint(v));
}

// ---- fused prep kernel: grid (256, 6); blockIdx.y selects task ----
__global__ void k_prep(const float* __restrict__ rel, const float* __restrict__ a1,
                       const float* __restrict__ a2, const float* __restrict__ fr,
                       const float* __restrict__ f1, const float* __restrict__ f2,
                       const float* __restrict__ ent, int N, int F) {
  const int sel = blockIdx.y;
  const int tid = threadIdx.x;

  if (sel == 0) {
    if (blockIdx.x >= (FPAD * BB) / 256) return;
    __shared__ __align__(16) float q[3][BB][EE];
    for (int i = tid; i < 3 * BB * EE; i += 256) {
      int t = i / (BB * EE), rem = i - t * (BB * EE);
      int b = rem / EE, e = rem - b * EE;
      const float* s = (t == 0) ? rel : (t == 1 ? a1 : a2);
      q[t][b][e] = s[b * EE + e];
    }
    __syncthreads();
    int idx = blockIdx.x * 256 + tid;
    int f = idx >> 3, b = idx & 7;
    if (f >= F) {
      g_Ab[0][f][b] = __float2bfloat16(CUDART_INF_F);
      g_Ab[1][f][b] = __float2bfloat16(CUDART_INF_F);
      return;
    }
    const float4* pr = (const float4*)(fr + (size_t)f * EE);
    const float4* p1 = (const float4*)(f1 + (size_t)f * EE);
    const float4* p2 = (const float4*)(f2 + (size_t)f * EE);
    float sr = 0.f, s1v = 0.f, s2v = 0.f, n1 = 0.f, n2 = 0.f;
#pragma unroll 5
    for (int e4 = 0; e4 < EE / 4; e4++) {
      float4 vr = pr[e4], v1 = p1[e4], v2 = p2[e4];
      n1 += v1.x * v1.x + v1.y * v1.y + v1.z * v1.z + v1.w * v1.w;
      n2 += v2.x * v2.x + v2.y * v2.y + v2.z * v2.z + v2.w * v2.w;
      float4 qr = *(const float4*)&q[0][b][e4 * 4];
      float4 q1 = *(const float4*)&q[1][b][e4 * 4];
      float4 q2 = *(const float4*)&q[2][b][e4 * 4];
      float t;
      t = qr.x - vr.x; sr += t * t;  t = qr.y - vr.y; sr += t * t;
      t = qr.z - vr.z; sr += t * t;  t = qr.w - vr.w; sr += t * t;
      t = q1.x - v1.x; s1v += t * t; t = q1.y - v1.y; s1v += t * t;
      t = q1.z - v1.z; s1v += t * t; t = q1.w - v1.w; s1v += t * t;
      t = q2.x - v2.x; s2v += t * t; t = q2.y - v2.y; s2v += t * t;
      t = q2.z - v2.z; s2v += t * t; t = q2.w - v2.w; s2v += t * t;
    }
    g_Ab[0][f][b] = __float2bfloat16(sr + s1v + n2);  // sp pairs with fa2
    g_Ab[1][f][b] = __float2bfloat16(sr + s2v + n1);  // po pairs with fa1
  } else if (sel == 1) {
    if (blockIdx.x >= FPAD / 256) return;
    int n = blockIdx.x * 256 + tid;
    if (n >= N) return;
    const float4* e4p = (const float4*)ent;
    float s = 0.f;
#pragma unroll
    for (int qq = 0; qq < EE / 4; qq++) {
      float4 v = e4p[n * (EE / 4) + qq];
      s += v.x * v.x + v.y * v.y + v.z * v.z + v.w * v.w;
    }
    g_e2[n] = s;
  } else if (sel <= 4) {
    // vectorized swizzled convert: one 16B granule (8 cols) per thread
    int gi = blockIdx.x * 256 + tid;      // 0..65535
    int r = gi >> 4, gg = gi & 15;
    const float* src = (sel == 2) ? ent : (sel == 3 ? f2 : f1);
    int rows = (sel == 2) ? N : F;
    float scale = (sel == 2) ? -2.0f : 1.0f;
    __nv_bfloat16 h[8];
#pragma unroll
    for (int k = 0; k < 8; k++) {
      int j = gg * 8 + k;
      float v = (r < rows && j < EE) ? scale * src[(size_t)r * EE + j] : 0.f;
      h[k] = __float2bfloat16(v);
    }
    int half = gg >> 3;
    unsigned bih = (gg & 7) * 16;
    unsigned off;
    char* dst;
    if (sel == 2) {
      off = (unsigned)(r >> 6) * 16384u + half * 8192u + swz((r & 63) * 128 + bih);
      dst = (char*)g_eb;
    } else {
      off = (unsigned)(r >> 7) * 32768u + half * 16384u + swz((r & 127) * 128 + bih);
      dst = (char*)g_fb[sel - 3];
    }
    *(uint4*)(dst + off) = *(uint4*)h;
  } else {
    // init: 2*BB*FPAD = 65536 floats -> exactly 256 blocks x 256 threads
    int i = blockIdx.x * 256 + tid;
    ((float*)g_min)[i] = CUDART_INF_F;
    if (i < 2 * (FPAD / NTILE)) ((int*)g_cnt)[i] = 0;
  }
}

// ---- main HMMA kernel (bulk staging, software-pipelined MMA/epilogue) ----
__global__ __launch_bounds__(256, 2) void k_main(float* __restrict__ out, int N) {
  extern __shared__ char sm[];
  const int tid = threadIdx.x;
  const int wid = tid >> 5;
  const int lane = tid & 31;
  const unsigned smb = smem_u32(sm);
  const int z = blockIdx.z;
  const int n0 = blockIdx.x * NTILE;
  const int f0base = blockIdx.y * (FPAD / FSPLIT);
  const int NCH = (FPAD / FSPLIT) / FCH;   // 16
  const char* fbB = (const char*)g_fb[z];
  const char* ebB = (const char*)g_eb;
  const unsigned mbF = smb + SM_MBAR;       // full[0], full[1]
  const unsigned mbE = smb + SM_MBAR + 16;  // empty[0], empty[1]

  const int wn = wid & 1, wf = wid >> 1;   // warp grid 2(n) x 4(f)
  const int g = lane >> 2, tl = lane & 3;
  const int lrow = lane & 7, mm = lane >> 3;

  // ldmatrix per-lane bases
  const int xoff = 16 * (mm >> 1);
  unsigned aRowOff[2], aXor[2];
#pragma unroll
  for (int mi = 0; mi < 2; mi++) {
    int r = 32 * wn + 16 * mi + lrow + 8 * (mm & 1);
    aRowOff[mi] = r * 128;
    aXor[mi] = (r & 7) * 16;
  }
  unsigned bRowOff[2], bXor[2];
#pragma unroll
  for (int njp = 0; njp < 2; njp++) {
    int r = 32 * wf + 16 * njp + lrow + 8 * (mm & 1);
    bRowOff[njp] = r * 128;
    bXor[njp] = (r & 7) * 16;
  }

  auto fSrc = [&](int c) { return fbB + (size_t)(f0base + c * FCH) * 256; };
  auto aSrc = [&](int c) { return (const char*)&g_Ab[z][f0base + c * FCH][0]; };

  if (tid == 0) {
    mbar_init(mbF, 1);
    mbar_init(mbF + 8, 1);
    mbar_init(mbE, 256);
    mbar_init(mbE + 8, 256);
  }
  __syncthreads();
  if (tid == 0) {
    mbar_expect(mbF, ENT_BYTES + FACT_BUF + A_BUF);
    bulk_g2s(smb + SM_ENT, ebB + (size_t)n0 * 256, ENT_BYTES, mbF);
    bulk_g2s(smb + SM_FACT, fSrc(0), FACT_BUF, mbF);
    bulk_g2s(smb + SM_A, aSrc(0), A_BUF, mbF);
    mbar_expect(mbF + 8, FACT_BUF + A_BUF);
    bulk_g2s(smb + SM_FACT + FACT_BUF, fSrc(1), FACT_BUF, mbF + 8);
    bulk_g2s(smb + SM_A + A_BUF, aSrc(1), A_BUF, mbF + 8);
  }

  uint32_t rmP[2][2][4];   // [mi][rowhalf][b-pair], bf16x2, init +INF|+INF
#pragma unroll
  for (int mi = 0; mi < 2; mi++)
#pragma unroll
    for (int h = 0; h < 2; h++)
#pragma unroll
      for (int j = 0; j < 4; j++) rmP[mi][h][j] = 0x7F807F80u;

  float acc0[2][4][4], acc1[2][4][4];   // double accumulators (pipelined)

  // fragment-load + MMA for the chunk resident in smem buffer `buf`
  auto compute = [&](int buf, float (*acc)[4][4]) {
#pragma unroll
    for (int mi = 0; mi < 2; mi++)
#pragma unroll
      for (int nj = 0; nj < 4; nj++)
#pragma unroll
        for (int k = 0; k < 4; k++) acc[mi][nj][k] = 0.f;
    const unsigned fBase = smb + SM_FACT + buf * FACT_BUF;
#pragma unroll
    for (int ks = 0; ks < NKS; ks++) {
      const int half = (ks >= 4);
      const int kb = (ks - (half ? 4 : 0)) * 32 + xoff;
      const unsigned aB = smb + SM_ENT + half * ENT_HALF;
      const unsigned bB = fBase + half * FACT_HALF;
      uint32_t af[2][4];
#pragma unroll
      for (int mi = 0; mi < 2; mi++)
        ldmx4(af[mi], aB + aRowOff[mi] + ((unsigned)kb ^ aXor[mi]));
      uint32_t bf[2][4];
#pragma unroll
      for (int njp = 0; njp < 2; njp++)
        ldmx4(bf[njp], bB + bRowOff[njp] + ((unsigned)kb ^ bXor[njp]));
#pragma unroll
      for (int mi = 0; mi < 2; mi++)
#pragma unroll
        for (int njp = 0; njp < 2; njp++) {
          mma16816(acc[mi][2 * njp],     af[mi], bf[njp][0], bf[njp][2]);
          mma16816(acc[mi][2 * njp + 1], af[mi], bf[njp][1], bf[njp][3]);
        }
    }
  };

  // packed bf16x2 epilogue: rm = min(rm, A + d)
  auto epilogue = [&](int buf, const float (*acc)[4][4]) {
    const uint32_t* As = (const uint32_t*)(sm + SM_A + buf * A_BUF);
#pragma unroll
    for (int nj = 0; nj < 4; nj++) {
      const int c0 = 32 * wf + 8 * nj + 2 * tl;
      uint4 A0 = *(const uint4*)(As + c0 * 4);       // col c0:  b0..7 (4 bf16x2)
      uint4 A1 = *(const uint4*)(As + c0 * 4 + 4);   // col c0+1
#pragma unroll
      for (int mi = 0; mi < 2; mi++) {
        const float* d = acc[mi][nj];
#pragma unroll
        for (int h = 0; h < 2; h++) {
          uint32_t d0 = bcvt2(d[h * 2]);
          uint32_t d1 = bcvt2(d[h * 2 + 1]);
          uint32_t* r = rmP[mi][h];
          r[0] = minbf2(r[0], minbf2(addbf2(A0.x, d0), addbf2(A1.x, d1)));
          r[1] = minbf2(r[1], minbf2(addbf2(A0.y, d0), addbf2(A1.y, d1)));
          r[2] = minbf2(r[2], minbf2(addbf2(A0.z, d0), addbf2(A1.z, d1)));
          r[3] = minbf2(r[3], minbf2(addbf2(A0.w, d0), addbf2(A1.w, d1)));
        }
      }
    }
  };

  // prologue: chunk 0 MMA
  mwait(mbF, 0);
  compute(0, acc0);

  for (int c = 0; c < NCH; c++) {
    const int buf = c & 1;
    const unsigned ph = (c >> 1) & 1;
    // compute chunk c+1 first (hides HMMA latency behind chunk c's epilogue)
    if (c + 1 < NCH) {
      mwait(mbF + 8 * (buf ^ 1), ((c + 1) >> 1) & 1);
      compute(buf ^ 1, buf ? acc0 : acc1);
    }
    // epilogue of chunk c (acc long since ready)
    epilogue(buf, buf ? acc1 : acc0);
    // release buf: epilogue read As[buf]; fragments of chunk c were read earlier
    mbar_arrive(mbE + 8 * buf);
    if (c + 2 < NCH && tid == 0) {
      mwait(mbE + 8 * buf, ph);
      mbar_expect(mbF + 8 * buf, FACT_BUF + A_BUF);
      bulk_g2s(smb + SM_FACT + buf * FACT_BUF, fSrc(c + 2), FACT_BUF, mbF + 8 * buf);
      bulk_g2s(smb + SM_A + buf * A_BUF, aSrc(c + 2), A_BUF, mbF + 8 * buf);
    }
  }

  // reduce across the 4 tl lanes sharing each row, then atomics
#pragma unroll
  for (int mi = 0; mi < 2; mi++)
#pragma unroll
    for (int h = 0; h < 2; h++)
#pragma unroll
      for (int j = 0; j < 4; j++) {
        uint32_t v = rmP[mi][h][j];
        v = minbf2(v, __shfl_xor_sync(0xffffffffu, v, 1));
        v = minbf2(v, __shfl_xor_sync(0xffffffffu, v, 2));
        rmP[mi][h][j] = v;
      }
  if (tl == 0) {
#pragma unroll
    for (int mi = 0; mi < 2; mi++)
#pragma unroll
      for (int h = 0; h < 2; h++) {
        int n = n0 + 32 * wn + 16 * mi + 8 * h + g;
        if (n < N) {
#pragma unroll
          for (int j = 0; j < 4; j++) {
            uint32_t v = rmP[mi][h][j];
            float lo = __uint_as_float((v & 0xFFFFu) << 16);
            float hi = __uint_as_float(v & 0xFFFF0000u);
            atomicMinF(&g_min[z][2 * j][n], lo);
            atomicMinF(&g_min[z][2 * j + 1][n], hi);
          }
        }
      }
  }

  // fused finalize: last CTA for this (z, n-tile) writes the outputs
  __shared__ int s_last;
  __threadfence();
  __syncthreads();
  if (tid == 0)
    s_last = atomicAdd(&g_cnt[z][blockIdx.x], 1);
  __syncthreads();
  if (s_last == FSPLIT - 1) {
    __threadfence();
    for (int o = tid; o < BB * NTILE; o += 256) {
      int b = o / NTILE, nl = o - (o / NTILE) * NTILE;
      int n = n0 + nl;
      if (n < N) {
        float d2 = fmaxf(g_min[z][b][n] + g_e2[n], 0.f);
        out[((size_t)z * BB + b) * N + n] = expf(-0.5f * d2);
      }
    }
  }
}

// ---------------------------------------------------------------------------
extern "C" void kernel_launch(void* const* d_in, const int* in_sizes, int n_in,
                              void* d_out, int out_size) {
  const float* rel = (const float*)d_in[0];
  const float* a1  = (const float*)d_in[1];
  const float* a2  = (const float*)d_in[2];
  const float* fr  = (const float*)d_in[3];
  const float* f1  = (const float*)d_in[4];
  const float* f2  = (const float*)d_in[5];
  const float* ent = (const float*)d_in[6];
  int F = in_sizes[3] / EE;
  int N = in_sizes[6] / EE;

  cudaFuncSetAttribute(k_main, cudaFuncAttributeMaxDynamicSharedMemorySize, SM_TOTAL);

  dim3 pgrid(256, 6);
  k_prep<<<pgrid, 256>>>(rel, a1, a2, fr, f1, f2, ent, N, F);

  dim3 grid(FPAD / NTILE, FSPLIT, 2);     // 64 x 2 x 2 = 256 CTAs, ~2/SM
  k_main<<<grid, 256, SM_TOTAL>>>((float*)d_out, N);
}

// round 13
// speedup vs baseline: 2.1103x; 2.1103x over previous
#include <cuda_runtime.h>
#include <cuda_bf16.h>
#include <math_constants.h>
#include <cstdint>

#define BB 8
#define EE 100
#define FPAD 4096
#define NTILE 64          // n rows per CTA tile
#define FCH 256           // f cols per chunk
#define KROW 128          // bf16 per logical row (2 halves of 64)
#define NKS 7             // 7 x k16 = 112 (zeros past 99 contribute 0)

// smem layout
#define ENT_HALF 8192                   // 64 rows x 128B
#define FACT_HALF 32768                 // 256 rows x 128B
#define ENT_BYTES (2*ENT_HALF)          // 16KB
#define FACT_BUF (2*FACT_HALF)          // 64KB per chunk
#define SM_ENT 0
#define SM_FACT ENT_BYTES               // 2 buffers x 64KB
#define SM_A (SM_FACT + 2*FACT_BUF)     // 2 buffers of [256 f][8 b] bf16
#define A_BUF 4096
#define SM_MBAR (SM_A + 2*A_BUF)        // full0, full1, empty0, empty1
#define SM_TOTAL (SM_MBAR + 32)         // 155680 B (1 CTA/SM)

// ---- device scratch ----
__device__ __nv_bfloat16 g_Ab[2][FPAD][BB];    // A transposed (bf16), +INF for f>=F
__device__ float g_e2[FPAD];
// PRE-SWIZZLED tiled layouts (written by k_prep, bulk-copied by k_main):
// g_eb: [tile(64 rows)][half][8KB swizzled]   (-2*ent)
// g_fb: [z][chunk(256 rows)][half][32KB swizzled]
__device__ __nv_bfloat16 g_eb[FPAD * KROW];
__device__ __nv_bfloat16 g_fb[2][FPAD * KROW];

// ---- helpers ----
__device__ __forceinline__ unsigned swz(unsigned b) { return b ^ ((b >> 3) & 0x70); }
__device__ __forceinline__ unsigned smem_u32(const void* p) {
  return (unsigned)__cvta_generic_to_shared(p);
}
__device__ __forceinline__ void mbar_init(unsigned a, unsigned cnt) {
  asm volatile("mbarrier.init.shared.b64 [%0], %1;" :: "r"(a), "r"(cnt) : "memory");
}
__device__ __forceinline__ void mbar_expect(unsigned a, unsigned tx) {
  asm volatile("mbarrier.arrive.expect_tx.shared.b64 _, [%0], %1;"
               :: "r"(a), "r"(tx) : "memory");
}
__device__ __forceinline__ void mbar_arrive(unsigned a) {
  asm volatile("mbarrier.arrive.release.cta.shared::cta.b64 _, [%0];"
               :: "r"(a) : "memory");
}
__device__ __forceinline__ void bulk_g2s(unsigned dst, const void* src,
                                         unsigned bytes, unsigned mbar) {
  asm volatile(
    "cp.async.bulk.shared::cluster.global.mbarrier::complete_tx::bytes "
    "[%0], [%1], %2, [%3];"
    :: "r"(dst), "l"(src), "r"(bytes), "r"(mbar) : "memory");
}
__device__ __forceinline__ void mwait(unsigned a, unsigned par) {
  asm volatile("{\n\t.reg .pred P;\n\t"
               "W%=:\n\tmbarrier.try_wait.parity.acquire.cta.shared::cta.b64 P, [%0], %1, 0x989680;\n\t"
               "@P bra.uni D%=;\n\tbra.uni W%=;\n\tD%=:\n\t}"
               :: "r"(a), "r"(par) : "memory");
}
__device__ __forceinline__ void ldmx4(uint32_t* r, unsigned addr) {
  asm volatile("ldmatrix.sync.aligned.m8n8.x4.shared.b16 {%0,%1,%2,%3}, [%4];"
               : "=r"(r[0]), "=r"(r[1]), "=r"(r[2]), "=r"(r[3]) : "r"(addr));
}
__device__ __forceinline__ void mma16816(float* c, const uint32_t* a,
                                         uint32_t b0, uint32_t b1) {
  asm volatile("mma.sync.aligned.m16n8k16.row.col.f32.bf16.bf16.f32 "
               "{%0,%1,%2,%3}, {%4,%5,%6,%7}, {%8,%9}, {%0,%1,%2,%3};"
               : "+f"(c[0]), "+f"(c[1]), "+f"(c[2]), "+f"(c[3])
               : "r"(a[0]), "r"(a[1]), "r"(a[2]), "r"(a[3]), "r"(b0), "r"(b1));
}
__device__ __forceinline__ uint32_t bcvt2(float x) {
  uint32_t r; asm("cvt.rn.bf16x2.f32 %0, %1, %1;" : "=r"(r) : "f"(x)); return r;
}
__device__ __forceinline__ uint32_t addbf2(uint32_t a, uint32_t b) {
  uint32_t r; asm("add.rn.bf16x2 %0, %1, %2;" : "=r"(r) : "r"(a), "r"(b)); return r;
}
__device__ __forceinline__ uint32_t minbf2(uint32_t a, uint32_t b) {
  uint32_t r; asm("min.bf16x2 %0, %1, %2;" : "=r"(r) : "r"(a), "r"(b)); return r;
}

// ---- fused prep kernel: grid (256, 5); blockIdx.y selects task ----
__global__ void k_prep(const float* __restrict__ rel, const float* __restrict__ a1,
                       const float* __restrict__ a2, const float* __restrict__ fr,
                       const float* __restrict__ f1, const float* __restrict__ f2,
                       const float* __restrict__ ent, int N, int F) {
  const int sel = blockIdx.y;
  const int tid = threadIdx.x;

  if (sel == 0) {
    if (blockIdx.x >= (FPAD * BB) / 256) return;
    __shared__ __align__(16) float q[3][BB][EE];
    for (int i = tid; i < 3 * BB * EE; i += 256) {
      int t = i / (BB * EE), rem = i - t * (BB * EE);
      int b = rem / EE, e = rem - b * EE;
      const float* s = (t == 0) ? rel : (t == 1 ? a1 : a2);
      q[t][b][e] = s[b * EE + e];
    }
    __syncthreads();
    int idx = blockIdx.x * 256 + tid;
    int f = idx >> 3, b = idx & 7;
    if (f >= F) {
      g_Ab[0][f][b] = __float2bfloat16(CUDART_INF_F);
      g_Ab[1][f][b] = __float2bfloat16(CUDART_INF_F);
      return;
    }
    const float4* pr = (const float4*)(fr + (size_t)f * EE);
    const float4* p1 = (const float4*)(f1 + (size_t)f * EE);
    const float4* p2 = (const float4*)(f2 + (size_t)f * EE);
    float sr = 0.f, s1v = 0.f, s2v = 0.f, n1 = 0.f, n2 = 0.f;
#pragma unroll 5
    for (int e4 = 0; e4 < EE / 4; e4++) {
      float4 vr = pr[e4], v1 = p1[e4], v2 = p2[e4];
      n1 += v1.x * v1.x + v1.y * v1.y + v1.z * v1.z + v1.w * v1.w;
      n2 += v2.x * v2.x + v2.y * v2.y + v2.z * v2.z + v2.w * v2.w;
      float4 qr = *(const float4*)&q[0][b][e4 * 4];
      float4 q1 = *(const float4*)&q[1][b][e4 * 4];
      float4 q2 = *(const float4*)&q[2][b][e4 * 4];
      float t;
      t = qr.x - vr.x; sr += t * t;  t = qr.y - vr.y; sr += t * t;
      t = qr.z - vr.z; sr += t * t;  t = qr.w - vr.w; sr += t * t;
      t = q1.x - v1.x; s1v += t * t; t = q1.y - v1.y; s1v += t * t;
      t = q1.z - v1.z; s1v += t * t; t = q1.w - v1.w; s1v += t * t;
      t = q2.x - v2.x; s2v += t * t; t = q2.y - v2.y; s2v += t * t;
      t = q2.z - v2.z; s2v += t * t; t = q2.w - v2.w; s2v += t * t;
    }
    g_Ab[0][f][b] = __float2bfloat16(sr + s1v + n2);  // sp pairs with fa2
    g_Ab[1][f][b] = __float2bfloat16(sr + s2v + n1);  // po pairs with fa1
  } else if (sel == 1) {
    if (blockIdx.x >= FPAD / 256) return;
    int n = blockIdx.x * 256 + tid;
    if (n >= N) return;
    const float4* e4p = (const float4*)ent;
    float s = 0.f;
#pragma unroll
    for (int qq = 0; qq < EE / 4; qq++) {
      float4 v = e4p[n * (EE / 4) + qq];
      s += v.x * v.x + v.y * v.y + v.z * v.z + v.w * v.w;
    }
    g_e2[n] = s;
  } else {
    // vectorized swizzled convert: one 16B granule (8 cols) per thread
    int gi = blockIdx.x * 256 + tid;      // 0..65535
    int r = gi >> 4, gg = gi & 15;
    const float* src = (sel == 2) ? ent : (sel == 3 ? f2 : f1);
    int rows = (sel == 2) ? N : F;
    float scale = (sel == 2) ? -2.0f : 1.0f;
    __nv_bfloat16 h[8];
#pragma unroll
    for (int k = 0; k < 8; k++) {
      int j = gg * 8 + k;
      float v = (r < rows && j < EE) ? scale * src[(size_t)r * EE + j] : 0.f;
      h[k] = __float2bfloat16(v);
    }
    int half = gg >> 3;
    unsigned bih = (gg & 7) * 16;
    unsigned off;
    char* dst;
    if (sel == 2) {
      // ent: 64-row tiles, two 8KB halves
      off = (unsigned)(r >> 6) * 16384u + half * 8192u + swz((r & 63) * 128 + bih);
      dst = (char*)g_eb;
    } else {
      // fact: 256-row chunks, two 32KB halves
      off = (unsigned)(r >> 8) * 65536u + half * 32768u + swz((r & 255) * 128 + bih);
      dst = (char*)g_fb[sel - 3];
    }
    *(uint4*)(dst + off) = *(uint4*)h;
  }
}

// ---- main HMMA kernel: 1 CTA/SM, hoisted ent fragments, smem finalize ----
__global__ __launch_bounds__(256, 1) void k_main(float* __restrict__ out, int N) {
  extern __shared__ char sm[];
  const int tid = threadIdx.x;
  const int wid = tid >> 5;
  const int lane = tid & 31;
  const unsigned smb = smem_u32(sm);
  const int z = blockIdx.y;
  const int n0 = blockIdx.x * NTILE;
  const int NCH = FPAD / FCH;              // 16
  const char* fbB = (const char*)g_fb[z];
  const char* ebB = (const char*)g_eb;
  const unsigned mbF = smb + SM_MBAR;       // full[0], full[1]
  const unsigned mbE = smb + SM_MBAR + 16;  // empty[0], empty[1]

  const int wn = wid & 1, wf = wid >> 1;   // warp grid 2(n) x 4(f); warp tile 32n x 64f
  const int g = lane >> 2, tl = lane & 3;
  const int lrow = lane & 7, mm = lane >> 3;

  // ldmatrix per-lane bases
  const int xoff = 16 * (mm >> 1);
  unsigned aRowOff[2], aXor[2];
#pragma unroll
  for (int mi = 0; mi < 2; mi++) {
    int r = 32 * wn + 16 * mi + lrow + 8 * (mm & 1);
    aRowOff[mi] = r * 128;
    aXor[mi] = (r & 7) * 16;
  }
  unsigned bRowOff[4], bXor[4];
#pragma unroll
  for (int njp = 0; njp < 4; njp++) {
    int r = 64 * wf + 16 * njp + lrow + 8 * (mm & 1);
    bRowOff[njp] = r * 128;
    bXor[njp] = (r & 7) * 16;
  }

  auto fSrc = [&](int c) { return fbB + (size_t)c * FCH * 256; };
  auto aSrc = [&](int c) { return (const char*)&g_Ab[z][c * FCH][0]; };

  if (tid == 0) {
    mbar_init(mbF, 1);
    mbar_init(mbF + 8, 1);
    mbar_init(mbE, 256);
    mbar_init(mbE + 8, 256);
  }
  __syncthreads();
  if (tid == 0) {
    mbar_expect(mbF, ENT_BYTES + FACT_BUF + A_BUF);
    bulk_g2s(smb + SM_ENT, ebB + (size_t)n0 * 256, ENT_BYTES, mbF);
    bulk_g2s(smb + SM_FACT, fSrc(0), FACT_BUF, mbF);
    bulk_g2s(smb + SM_A, aSrc(0), A_BUF, mbF);
    mbar_expect(mbF + 8, FACT_BUF + A_BUF);
    bulk_g2s(smb + SM_FACT + FACT_BUF, fSrc(1), FACT_BUF, mbF + 8);
    bulk_g2s(smb + SM_A + A_BUF, aSrc(1), A_BUF, mbF + 8);
  }

  // wait chunk 0 (brings ent too) and hoist ALL ent fragments into registers
  mwait(mbF, 0);
  uint32_t afH[NKS][2][4];
#pragma unroll
  for (int ks = 0; ks < NKS; ks++) {
    const int half = (ks >= 4);
    const int kb = (ks - (half ? 4 : 0)) * 32 + xoff;
    const unsigned aB = smb + SM_ENT + half * ENT_HALF;
#pragma unroll
    for (int mi = 0; mi < 2; mi++)
      ldmx4(afH[ks][mi], aB + aRowOff[mi] + ((unsigned)kb ^ aXor[mi]));
  }

  uint32_t rmP[2][2][4];   // [mi][rowhalf][b-pair], bf16x2, init +INF|+INF
#pragma unroll
  for (int mi = 0; mi < 2; mi++)
#pragma unroll
    for (int h = 0; h < 2; h++)
#pragma unroll
      for (int j = 0; j < 4; j++) rmP[mi][h][j] = 0x7F807F80u;

  for (int c = 0; c < NCH; c++) {
    const int buf = c & 1;
    const unsigned ph = (c >> 1) & 1;
    mwait(mbF + 8 * buf, ph);   // immediate for c==0 (already flipped)

    float acc[2][8][4];
#pragma unroll
    for (int mi = 0; mi < 2; mi++)
#pragma unroll
      for (int nj = 0; nj < 8; nj++)
#pragma unroll
        for (int k = 0; k < 4; k++) acc[mi][nj][k] = 0.f;

    const unsigned fBase = smb + SM_FACT + buf * FACT_BUF;
#pragma unroll
    for (int ks = 0; ks < NKS; ks++) {
      const int half = (ks >= 4);
      const int kb = (ks - (half ? 4 : 0)) * 32 + xoff;
      const unsigned bB = fBase + half * FACT_HALF;
      uint32_t bf[4][4];
#pragma unroll
      for (int njp = 0; njp < 4; njp++)
        ldmx4(bf[njp], bB + bRowOff[njp] + ((unsigned)kb ^ bXor[njp]));
#pragma unroll
      for (int mi = 0; mi < 2; mi++)
#pragma unroll
        for (int njp = 0; njp < 4; njp++) {
          mma16816(acc[mi][2 * njp],     afH[ks][mi], bf[njp][0], bf[njp][2]);
          mma16816(acc[mi][2 * njp + 1], afH[ks][mi], bf[njp][1], bf[njp][3]);
        }
    }

    // packed bf16x2 epilogue: rm = min(rm, A + d)
    const uint32_t* As = (const uint32_t*)(sm + SM_A + buf * A_BUF);
#pragma unroll
    for (int nj = 0; nj < 8; nj++) {
      const int c0 = 64 * wf + 8 * nj + 2 * tl;
      uint4 A0 = *(const uint4*)(As + c0 * 4);       // col c0:  b0..7 (4 bf16x2)
      uint4 A1 = *(const uint4*)(As + c0 * 4 + 4);   // col c0+1
#pragma unroll
      for (int mi = 0; mi < 2; mi++) {
        const float* d = acc[mi][nj];
#pragma unroll
        for (int h = 0; h < 2; h++) {
          uint32_t d0 = bcvt2(d[h * 2]);
          uint32_t d1 = bcvt2(d[h * 2 + 1]);
          uint32_t* r = rmP[mi][h];
          r[0] = minbf2(r[0], minbf2(addbf2(A0.x, d0), addbf2(A1.x, d1)));
          r[1] = minbf2(r[1], minbf2(addbf2(A0.y, d0), addbf2(A1.y, d1)));
          r[2] = minbf2(r[2], minbf2(addbf2(A0.z, d0), addbf2(A1.z, d1)));
          r[3] = minbf2(r[3], minbf2(addbf2(A0.w, d0), addbf2(A1.w, d1)));
        }
      }
    }

    // consumer release + producer refill
    mbar_arrive(mbE + 8 * buf);
    if (c + 2 < NCH && tid == 0) {
      mwait(mbE + 8 * buf, ph);
      mbar_expect(mbF + 8 * buf, FACT_BUF + A_BUF);
      bulk_g2s(smb + SM_FACT + buf * FACT_BUF, fSrc(c + 2), FACT_BUF, mbF + 8 * buf);
      bulk_g2s(smb + SM_A + buf * A_BUF, aSrc(c + 2), A_BUF, mbF + 8 * buf);
    }
  }

  // reduce across tl lanes (f columns within warp), then across warps in smem
#pragma unroll
  for (int mi = 0; mi < 2; mi++)
#pragma unroll
    for (int h = 0; h < 2; h++)
#pragma unroll
      for (int j = 0; j < 4; j++) {
        uint32_t v = rmP[mi][h][j];
        v = minbf2(v, __shfl_xor_sync(0xffffffffu, v, 1));
        v = minbf2(v, __shfl_xor_sync(0xffffffffu, v, 2));
        rmP[mi][h][j] = v;
      }

  uint32_t* s_rm = (uint32_t*)sm;   // [wf][n_local 64][4 b-pairs] = 4KB (ent region, done)
  __syncthreads();                  // everyone past chunk loop before reuse
  if (tl == 0) {
#pragma unroll
    for (int mi = 0; mi < 2; mi++)
#pragma unroll
      for (int h = 0; h < 2; h++) {
        int nl = 32 * wn + 16 * mi + 8 * h + g;
#pragma unroll
        for (int j = 0; j < 4; j++)
          s_rm[(wf * 64 + nl) * 4 + j] = rmP[mi][h][j];
      }
  }
  __syncthreads();

  // finalize: 256 threads cover 64 n x 4 b-pairs; min over 4 warps, exp, store
  {
    int nl = tid >> 2, j = tid & 3;
    uint32_t v = s_rm[nl * 4 + j];
    v = minbf2(v, s_rm[(64 + nl) * 4 + j]);
    v = minbf2(v, s_rm[(128 + nl) * 4 + j]);
    v = minbf2(v, s_rm[(192 + nl) * 4 + j]);
    int n = n0 + nl;
    if (n < N) {
      float e2 = g_e2[n];
      float lo = __uint_as_float((v & 0xFFFFu) << 16);
      float hi = __uint_as_float(v & 0xFFFF0000u);
      float d2a = fmaxf(lo + e2, 0.f);
      float d2b = fmaxf(hi + e2, 0.f);
      out[((size_t)z * BB + 2 * j) * N + n] = expf(-0.5f * d2a);
      out[((size_t)z * BB + 2 * j + 1) * N + n] = expf(-0.5f * d2b);
    }
  }
}

// ---------------------------------------------------------------------------
extern "C" void kernel_launch(void* const* d_in, const int* in_sizes, int n_in,
                              void* d_out, int out_size) {
  const float* rel = (const float*)d_in[0];
  const float* a1  = (const float*)d_in[1];
  const float* a2  = (const float*)d_in[2];
  const float* fr  = (const float*)d_in[3];
  const float* f1  = (const float*)d_in[4];
  const float* f2  = (const float*)d_in[5];
  const float* ent = (const float*)d_in[6];
  int F = in_sizes[3] / EE;
  int N = in_sizes[6] / EE;

  cudaFuncSetAttribute(k_main, cudaFuncAttributeMaxDynamicSharedMemorySize, SM_TOTAL);

  dim3 pgrid(256, 5);
  k_prep<<<pgrid, 256>>>(rel, a1, a2, fr, f1, f2, ent, N, F);

  dim3 grid(FPAD / NTILE, 2);     // 64 x 2 = 128 CTAs, 1/SM
  k_main<<<grid, 256, SM_TOTAL>>>((float*)d_out, N);
}

// round 14
// speedup vs baseline: 2.1222x; 1.0056x over previous
#include <cuda_runtime.h>
#include <cuda_bf16.h>
#include <math_constants.h>
#include <cstdint>

#define BB 8
#define EE 100
#define FPAD 4096
#define NTILE 64          // n rows per CTA tile
#define FCH 256           // f cols per chunk
#define KROW 128
#define NKS 7             // 7 x k16 = 112 (zeros past 99 contribute 0)
#define NCTA 128          // 64 n-tiles x 2 z; 1 CTA/SM, all co-resident

// smem layout
#define ENT_HALF 8192                   // 64 rows x 128B
#define FACT_HALF 32768                 // 256 rows x 128B
#define ENT_BYTES (2*ENT_HALF)          // 16KB
#define FACT_BUF (2*FACT_HALF)          // 64KB per chunk
#define SM_ENT 0
#define SM_FACT ENT_BYTES               // 2 buffers x 64KB
#define SM_A (SM_FACT + 2*FACT_BUF)     // 2 buffers of [256 f][8 b] bf16
#define A_BUF 4096
#define SM_MBAR (SM_A + 2*A_BUF)
#define SM_TOTAL (SM_MBAR + 32)         // 155680 B (1 CTA/SM)

// ---- device scratch ----
__device__ __nv_bfloat16 g_Ab[2][FPAD][BB];    // A transposed (bf16), +INF for f>=F
__device__ float g_e2[FPAD];
__device__ __nv_bfloat16 g_eb[FPAD * KROW];    // pre-swizzled -2*ent tiles
__device__ __nv_bfloat16 g_fb[2][FPAD * KROW]; // pre-swizzled fact chunks
__device__ int g_sync;                         // prep arrival counter
__device__ int g_done;                         // exit counter (resets g_sync)

// ---- helpers ----
__device__ __forceinline__ unsigned swz(unsigned b) { return b ^ ((b >> 3) & 0x70); }
__device__ __forceinline__ unsigned smem_u32(const void* p) {
  return (unsigned)__cvta_generic_to_shared(p);
}
__device__ __forceinline__ void mbar_init(unsigned a, unsigned cnt) {
  asm volatile("mbarrier.init.shared.b64 [%0], %1;" :: "r"(a), "r"(cnt) : "memory");
}
__device__ __forceinline__ void mbar_expect(unsigned a, unsigned tx) {
  asm volatile("mbarrier.arrive.expect_tx.shared.b64 _, [%0], %1;"
               :: "r"(a), "r"(tx) : "memory");
}
__device__ __forceinline__ void mbar_arrive(unsigned a) {
  asm volatile("mbarrier.arrive.release.cta.shared::cta.b64 _, [%0];"
               :: "r"(a) : "memory");
}
__device__ __forceinline__ void bulk_g2s(unsigned dst, const void* src,
                                         unsigned bytes, unsigned mbar) {
  asm volatile(
    "cp.async.bulk.shared::cluster.global.mbarrier::complete_tx::bytes "
    "[%0], [%1], %2, [%3];"
    :: "r"(dst), "l"(src), "r"(bytes), "r"(mbar) : "memory");
}
__device__ __forceinline__ void mwait(unsigned a, unsigned par) {
  asm volatile("{\n\t.reg .pred P;\n\t"
               "W%=:\n\tmbarrier.try_wait.parity.acquire.cta.shared::cta.b64 P, [%0], %1, 0x989680;\n\t"
               "@P bra.uni D%=;\n\tbra.uni W%=;\n\tD%=:\n\t}"
               :: "r"(a), "r"(par) : "memory");
}
__device__ __forceinline__ void ldmx4(uint32_t* r, unsigned addr) {
  asm volatile("ldmatrix.sync.aligned.m8n8.x4.shared.b16 {%0,%1,%2,%3}, [%4];"
               : "=r"(r[0]), "=r"(r[1]), "=r"(r[2]), "=r"(r[3]) : "r"(addr));
}
__device__ __forceinline__ void mma16816(float* c, const uint32_t* a,
                                         uint32_t b0, uint32_t b1) {
  asm volatile("mma.sync.aligned.m16n8k16.row.col.f32.bf16.bf16.f32 "
               "{%0,%1,%2,%3}, {%4,%5,%6,%7}, {%8,%9}, {%0,%1,%2,%3};"
               : "+f"(c[0]), "+f"(c[1]), "+f"(c[2]), "+f"(c[3])
               : "r"(a[0]), "r"(a[1]), "r"(a[2]), "r"(a[3]), "r"(b0), "r"(b1));
}
__device__ __forceinline__ uint32_t bcvt2(float x) {
  uint32_t r; asm("cvt.rn.bf16x2.f32 %0, %1, %1;" : "=r"(r) : "f"(x)); return r;
}
__device__ __forceinline__ uint32_t addbf2(uint32_t a, uint32_t b) {
  uint32_t r; asm("add.rn.bf16x2 %0, %1, %2;" : "=r"(r) : "r"(a), "r"(b)); return r;
}
__device__ __forceinline__ uint32_t minbf2(uint32_t a, uint32_t b) {
  uint32_t r; asm("min.bf16x2 %0, %1, %2;" : "=r"(r) : "r"(a), "r"(b)); return r;
}

// ===========================================================================
// Single fused kernel: inline prep -> grid barrier -> HMMA mainloop -> output
// ===========================================================================
__global__ __launch_bounds__(256, 1) void k_all(
    float* __restrict__ out,
    const float* __restrict__ rel, const float* __restrict__ a1,
    const float* __restrict__ a2, const float* __restrict__ fr,
    const float* __restrict__ f1, const float* __restrict__ f2,
    const float* __restrict__ ent, int N, int F) {
  extern __shared__ char sm[];
  const int tid = threadIdx.x;
  const int wid = tid >> 5;
  const int lane = tid & 31;
  const unsigned smb = smem_u32(sm);
  const int z = blockIdx.y;
  const int n0 = blockIdx.x * NTILE;
  const int flat = blockIdx.y * gridDim.x + blockIdx.x;   // 0..127
  const int NCH = FPAD / FCH;              // 16

  // ---------------- PREP PHASE (each CTA does a 1/128 slice) ----------------
  {
    // queries into smem (reused region; staging starts after barrier)
    float* q = (float*)sm;                 // [3][8][100]
    for (int i = tid; i < 3 * BB * EE; i += 256) {
      int t = i / (BB * EE), rem = i - t * (BB * EE);
      const float* s = (t == 0) ? rel : (t == 1 ? a1 : a2);
      q[i] = s[rem];
    }
    __syncthreads();

    // prepA: one (f,b) per thread; 128 CTAs x 256 = 32768 tasks
    {
      int idx = flat * 256 + tid;
      int f = idx >> 3, b = idx & 7;
      if (f >= F) {
        g_Ab[0][f][b] = __float2bfloat16(CUDART_INF_F);
        g_Ab[1][f][b] = __float2bfloat16(CUDART_INF_F);
      } else {
        const float4* pr = (const float4*)(fr + (size_t)f * EE);
        const float4* p1 = (const float4*)(f1 + (size_t)f * EE);
        const float4* p2 = (const float4*)(f2 + (size_t)f * EE);
        const float4* qr4 = (const float4*)(q + (0 * BB + b) * EE);
        const float4* q14 = (const float4*)(q + (1 * BB + b) * EE);
        const float4* q24 = (const float4*)(q + (2 * BB + b) * EE);
        float sr = 0.f, s1v = 0.f, s2v = 0.f, n1 = 0.f, n2 = 0.f;
#pragma unroll 5
        for (int e4 = 0; e4 < EE / 4; e4++) {
          float4 vr = pr[e4], v1 = p1[e4], v2 = p2[e4];
          n1 += v1.x * v1.x + v1.y * v1.y + v1.z * v1.z + v1.w * v1.w;
          n2 += v2.x * v2.x + v2.y * v2.y + v2.z * v2.z + v2.w * v2.w;
          float4 qr = qr4[e4], q1 = q14[e4], q2 = q24[e4];
          float t;
          t = qr.x - vr.x; sr += t * t;  t = qr.y - vr.y; sr += t * t;
          t = qr.z - vr.z; sr += t * t;  t = qr.w - vr.w; sr += t * t;
          t = q1.x - v1.x; s1v += t * t; t = q1.y - v1.y; s1v += t * t;
          t = q1.z - v1.z; s1v += t * t; t = q1.w - v1.w; s1v += t * t;
          t = q2.x - v2.x; s2v += t * t; t = q2.y - v2.y; s2v += t * t;
          t = q2.z - v2.z; s2v += t * t; t = q2.w - v2.w; s2v += t * t;
        }
        g_Ab[0][f][b] = __float2bfloat16(sr + s1v + n2);  // sp pairs with fa2
        g_Ab[1][f][b] = __float2bfloat16(sr + s2v + n1);  // po pairs with fa1
      }
    }

    // swizzled bf16 converts: 3 x 65536 granules; 6 per thread
#pragma unroll
    for (int i = 0; i < 6; i++) {
      int t = flat * 1536 + i * 256 + tid;
      int sel = t >> 16;                    // 0=ent, 1=f2(sp), 2=f1(po)
      int gi = t & 65535;
      int r = gi >> 4, gg = gi & 15;
      const float* src = (sel == 0) ? ent : (sel == 1 ? f2 : f1);
      int rows = (sel == 0) ? N : F;
      float scale = (sel == 0) ? -2.0f : 1.0f;
      __nv_bfloat16 h[8];
#pragma unroll
      for (int k = 0; k < 8; k++) {
        int j = gg * 8 + k;
        float v = (r < rows && j < EE) ? scale * src[(size_t)r * EE + j] : 0.f;
        h[k] = __float2bfloat16(v);
      }
      int half = gg >> 3;
      unsigned bih = (gg & 7) * 16;
      unsigned off;
      char* dst;
      if (sel == 0) {
        off = (unsigned)(r >> 6) * 16384u + half * 8192u + swz((r & 63) * 128 + bih);
        dst = (char*)g_eb;
      } else {
        off = (unsigned)(r >> 8) * 65536u + half * 32768u + swz((r & 255) * 128 + bih);
        dst = (char*)g_fb[sel - 1];
      }
      *(uint4*)(dst + off) = *(uint4*)h;
    }

    // e2 (first 16 CTAs)
    if (flat < 16) {
      int n = flat * 256 + tid;
      if (n < N) {
        const float4* e4p = (const float4*)ent;
        float s = 0.f;
#pragma unroll
        for (int qq = 0; qq < EE / 4; qq++) {
          float4 v = e4p[n * (EE / 4) + qq];
          s += v.x * v.x + v.y * v.y + v.z * v.z + v.w * v.w;
        }
        g_e2[n] = s;
      }
    }

    // grid-wide barrier (all 128 CTAs co-resident at 1 CTA/SM)
    __threadfence();
    __syncthreads();
    if (tid == 0) {
      atomicAdd(&g_sync, 1);
      while (atomicAdd(&g_sync, 0) < NCTA) { __nanosleep(64); }
    }
    __syncthreads();
  }

  // ---------------- MAIN GEMM PHASE ----------------
  const char* fbB = (const char*)g_fb[z];
  const char* ebB = (const char*)g_eb;
  const unsigned mbF = smb + SM_MBAR;       // full[0], full[1]
  const unsigned mbE = smb + SM_MBAR + 16;  // empty[0], empty[1]

  const int wn = wid & 1, wf = wid >> 1;   // warp grid 2(n) x 4(f); tile 32n x 64f
  const int g = lane >> 2, tl = lane & 3;
  const int lrow = lane & 7, mm = lane >> 3;

  const int xoff = 16 * (mm >> 1);
  unsigned aRowOff[2], aXor[2];
#pragma unroll
  for (int mi = 0; mi < 2; mi++) {
    int r = 32 * wn + 16 * mi + lrow + 8 * (mm & 1);
    aRowOff[mi] = r * 128;
    aXor[mi] = (r & 7) * 16;
  }
  unsigned bRowOff[4], bXor[4];
#pragma unroll
  for (int njp = 0; njp < 4; njp++) {
    int r = 64 * wf + 16 * njp + lrow + 8 * (mm & 1);
    bRowOff[njp] = r * 128;
    bXor[njp] = (r & 7) * 16;
  }

  auto fSrc = [&](int c) { return fbB + (size_t)c * FCH * 256; };
  auto aSrc = [&](int c) { return (const char*)&g_Ab[z][c * FCH][0]; };

  if (tid == 0) {
    mbar_init(mbF, 1);
    mbar_init(mbF + 8, 1);
    mbar_init(mbE, 256);
    mbar_init(mbE + 8, 256);
  }
  __syncthreads();
  if (tid == 0) {
    mbar_expect(mbF, ENT_BYTES + FACT_BUF + A_BUF);
    bulk_g2s(smb + SM_ENT, ebB + (size_t)n0 * 256, ENT_BYTES, mbF);
    bulk_g2s(smb + SM_FACT, fSrc(0), FACT_BUF, mbF);
    bulk_g2s(smb + SM_A, aSrc(0), A_BUF, mbF);
    mbar_expect(mbF + 8, FACT_BUF + A_BUF);
    bulk_g2s(smb + SM_FACT + FACT_BUF, fSrc(1), FACT_BUF, mbF + 8);
    bulk_g2s(smb + SM_A + A_BUF, aSrc(1), A_BUF, mbF + 8);
  }

  // hoist all ent fragments into registers (ent constant across chunks)
  mwait(mbF, 0);
  uint32_t afH[NKS][2][4];
#pragma unroll
  for (int ks = 0; ks < NKS; ks++) {
    const int half = (ks >= 4);
    const int kb = (ks - (half ? 4 : 0)) * 32 + xoff;
    const unsigned aB = smb + SM_ENT + half * ENT_HALF;
#pragma unroll
    for (int mi = 0; mi < 2; mi++)
      ldmx4(afH[ks][mi], aB + aRowOff[mi] + ((unsigned)kb ^ aXor[mi]));
  }

  uint32_t rmP[2][2][4];
#pragma unroll
  for (int mi = 0; mi < 2; mi++)
#pragma unroll
    for (int h = 0; h < 2; h++)
#pragma unroll
      for (int j = 0; j < 4; j++) rmP[mi][h][j] = 0x7F807F80u;

  for (int c = 0; c < NCH; c++) {
    const int buf = c & 1;
    const unsigned ph = (c >> 1) & 1;
    mwait(mbF + 8 * buf, ph);

    float acc[2][8][4];
#pragma unroll
    for (int mi = 0; mi < 2; mi++)
#pragma unroll
      for (int nj = 0; nj < 8; nj++)
#pragma unroll
        for (int k = 0; k < 4; k++) acc[mi][nj][k] = 0.f;

    const unsigned fBase = smb + SM_FACT + buf * FACT_BUF;
    auto loadB = [&](int ks, uint32_t (*dst)[4]) {
      const int half = (ks >= 4);
      const int kb = (ks - (half ? 4 : 0)) * 32 + xoff;
      const unsigned bB = fBase + half * FACT_HALF;
#pragma unroll
      for (int njp = 0; njp < 4; njp++)
        ldmx4(dst[njp], bB + bRowOff[njp] + ((unsigned)kb ^ bXor[njp]));
    };

    uint32_t bf[2][4][4];       // register double buffer for B fragments
    loadB(0, bf[0]);
#pragma unroll
    for (int ks = 0; ks < NKS; ks++) {
      if (ks + 1 < NKS) loadB(ks + 1, bf[(ks + 1) & 1]);
      const uint32_t (*bc)[4] = bf[ks & 1];
#pragma unroll
      for (int mi = 0; mi < 2; mi++)
#pragma unroll
        for (int njp = 0; njp < 4; njp++) {
          mma16816(acc[mi][2 * njp],     afH[ks][mi], bc[njp][0], bc[njp][2]);
          mma16816(acc[mi][2 * njp + 1], afH[ks][mi], bc[njp][1], bc[njp][3]);
        }
    }

    // packed bf16x2 epilogue: rm = min(rm, A + d)
    const uint32_t* As = (const uint32_t*)(sm + SM_A + buf * A_BUF);
#pragma unroll
    for (int nj = 0; nj < 8; nj++) {
      const int c0 = 64 * wf + 8 * nj + 2 * tl;
      uint4 A0 = *(const uint4*)(As + c0 * 4);
      uint4 A1 = *(const uint4*)(As + c0 * 4 + 4);
#pragma unroll
      for (int mi = 0; mi < 2; mi++) {
        const float* d = acc[mi][nj];
#pragma unroll
        for (int h = 0; h < 2; h++) {
          uint32_t d0 = bcvt2(d[h * 2]);
          uint32_t d1 = bcvt2(d[h * 2 + 1]);
          uint32_t* r = rmP[mi][h];
          r[0] = minbf2(r[0], minbf2(addbf2(A0.x, d0), addbf2(A1.x, d1)));
          r[1] = minbf2(r[1], minbf2(addbf2(A0.y, d0), addbf2(A1.y, d1)));
          r[2] = minbf2(r[2], minbf2(addbf2(A0.z, d0), addbf2(A1.z, d1)));
          r[3] = minbf2(r[3], minbf2(addbf2(A0.w, d0), addbf2(A1.w, d1)));
        }
      }
    }

    mbar_arrive(mbE + 8 * buf);
    if (c + 2 < NCH && tid == 0) {
      mwait(mbE + 8 * buf, ph);
      mbar_expect(mbF + 8 * buf, FACT_BUF + A_BUF);
      bulk_g2s(smb + SM_FACT + buf * FACT_BUF, fSrc(c + 2), FACT_BUF, mbF + 8 * buf);
      bulk_g2s(smb + SM_A + buf * A_BUF, aSrc(c + 2), A_BUF, mbF + 8 * buf);
    }
  }

  // reduce across tl lanes, then across warps in smem, then exp + store
#pragma unroll
  for (int mi = 0; mi < 2; mi++)
#pragma unroll
    for (int h = 0; h < 2; h++)
#pragma unroll
      for (int j = 0; j < 4; j++) {
        uint32_t v = rmP[mi][h][j];
        v = minbf2(v, __shfl_xor_sync(0xffffffffu, v, 1));
        v = minbf2(v, __shfl_xor_sync(0xffffffffu, v, 2));
        rmP[mi][h][j] = v;
      }

  uint32_t* s_rm = (uint32_t*)sm;
  __syncthreads();
  if (tl == 0) {
#pragma unroll
    for (int mi = 0; mi < 2; mi++)
#pragma unroll
      for (int h = 0; h < 2; h++) {
        int nl = 32 * wn + 16 * mi + 8 * h + g;
#pragma unroll
        for (int j = 0; j < 4; j++)
          s_rm[(wf * 64 + nl) * 4 + j] = rmP[mi][h][j];
      }
  }
  __syncthreads();
  {
    int nl = tid >> 2, j = tid & 3;
    uint32_t v = s_rm[nl * 4 + j];
    v = minbf2(v, s_rm[(64 + nl) * 4 + j]);
    v = minbf2(v, s_rm[(128 + nl) * 4 + j]);
    v = minbf2(v, s_rm[(192 + nl) * 4 + j]);
    int n = n0 + nl;
    if (n < N) {
      float e2 = g_e2[n];
      float lo = __uint_as_float((v & 0xFFFFu) << 16);
      float hi = __uint_as_float(v & 0xFFFF0000u);
      out[((size_t)z * BB + 2 * j) * N + n] = expf(-0.5f * fmaxf(lo + e2, 0.f));
      out[((size_t)z * BB + 2 * j + 1) * N + n] = expf(-0.5f * fmaxf(hi + e2, 0.f));
    }
  }

  // reset sync counters for next graph replay (last CTA out)
  if (tid == 0) {
    int r = atomicAdd(&g_done, 1);
    if (r == NCTA - 1) { g_sync = 0; g_done = 0; }
  }
}

// ---------------------------------------------------------------------------
extern "C" void kernel_launch(void* const* d_in, const int* in_sizes, int n_in,
                              void* d_out, int out_size) {
  const float* rel = (const float*)d_in[0];
  const float* a1  = (const float*)d_in[1];
  const float* a2  = (const float*)d_in[2];
  const float* fr  = (const float*)d_in[3];
  const float* f1  = (const float*)d_in[4];
  const float* f2  = (const float*)d_in[5];
  const float* ent = (const float*)d_in[6];
  int F = in_sizes[3] / EE;
  int N = in_sizes[6] / EE;

  cudaFuncSetAttribute(k_all, cudaFuncAttributeMaxDynamicSharedMemorySize, SM_TOTAL);

  dim3 grid(FPAD / NTILE, 2);     // 64 x 2 = 128 CTAs, 1/SM, all co-resident
  k_all<<<grid, 256, SM_TOTAL>>>((float*)d_out, rel, a1, a2, fr, f1, f2, ent, N, F);
}